// round 17
// baseline (speedup 1.0000x reference)
#include <cuda_runtime.h>
#include <cuda_bf16.h>
#include <cstdint>

#define SS   512
#define G4   512
#define HH   128
#define DD   128
#define VSZ  64000
#define BC   8
#define NCTA 128
#define NOPS 16

typedef unsigned int u32;
typedef unsigned long long u64;

// ---------------- device globals ----------------
// xg[token][j*4 + type] bf16: x-path precomputed with bias (i,f,g,o per j)
__device__ __align__(16) __nv_bfloat16 g_xg[(size_t)VSZ * G4];  // 64 MB

// ---------------- helpers ----------------
__device__ __forceinline__ u32 smem_u32(const void* p) {
    u32 a;
    asm("{ .reg .u64 t; cvta.to.shared.u64 t, %1; cvt.u32.u64 %0, t; }" : "=r"(a) : "l"(p));
    return a;
}
__device__ __forceinline__ void mma16816(float* d, const u32* a, const u32* b) {
    asm volatile(
        "mma.sync.aligned.m16n8k16.row.col.f32.bf16.bf16.f32 "
        "{%0,%1,%2,%3},{%4,%5,%6,%7},{%8,%9},{%0,%1,%2,%3};"
        : "+f"(d[0]), "+f"(d[1]), "+f"(d[2]), "+f"(d[3])
        : "r"(a[0]), "r"(a[1]), "r"(a[2]), "r"(a[3]), "r"(b[0]), "r"(b[1]));
}
__device__ __forceinline__ void ldsm_x2t(u32* r, u32 addr) {
    asm volatile("ldmatrix.sync.aligned.m8n8.x2.trans.shared.b16 {%0,%1},[%2];"
                 : "=r"(r[0]), "=r"(r[1]) : "r"(addr));
}
__device__ __forceinline__ void cp_async8(u32 dst, const void* src) {
    asm volatile("cp.async.ca.shared.global [%0], [%1], 8;"
                 :: "r"(dst), "l"(src) : "memory");
}
__device__ __forceinline__ void cp_commit() {
    asm volatile("cp.async.commit_group;" ::: "memory");
}
__device__ __forceinline__ void cp_wait1() {
    asm volatile("cp.async.wait_group 1;" ::: "memory");
}
__device__ __forceinline__ float ex2_ap(float x) {
    float y; asm("ex2.approx.f32 %0, %1;" : "=f"(y) : "f"(x)); return y;
}
__device__ __forceinline__ float rcp_ap(float x) {
    float y; asm("rcp.approx.f32 %0, %1;" : "=f"(y) : "f"(x)); return y;
}
__device__ __forceinline__ float tanh_ap(float x) {
    float y; asm("tanh.approx.f32 %0, %1;" : "=f"(y) : "f"(x)); return y;
}
__device__ __forceinline__ float sig_ap(float x) {
    return fmaf(tanh_ap(x * 0.5f), 0.5f, 0.5f);
}
// accurate tanh (output-path h_last capture only)
__device__ __forceinline__ float tanh_acc(float x) {
    return 1.f - 2.f * rcp_ap(1.f + ex2_ap(2.885390081777927f * x));
}
__device__ __forceinline__ float bf_lo(u32 p) { return __uint_as_float(p << 16); }
__device__ __forceinline__ float bf_hi(u32 p) { return __uint_as_float(p & 0xFFFF0000u); }
__device__ __forceinline__ u32 pack_bf2(float lo, float hi) {
    __nv_bfloat162 p = __floats2bfloat162_rn(lo, hi);
    return *(u32*)&p;
}

// ---------------- Phase A: xg = W_ih @ relu(emb) + bias, all tokens ----------------
#define XPITCH 272
__global__ void __launch_bounds__(256, 1)
phaseA_kernel(const float* __restrict__ emb, const float* __restrict__ Wih,
              const float* __restrict__ bih, const float* __restrict__ bhh) {
    __shared__ __align__(16) unsigned char sX[128 * XPITCH];
    const int tid = threadIdx.x;
    const int w = tid >> 5, lane = tid & 31;
    const int tokbase = blockIdx.x * 128;

    {
        int r = tid >> 1, half = tid & 1;
        const float* er = emb + (size_t)(tokbase + r) * DD + half * 64;
#pragma unroll 4
        for (int cc = 0; cc < 64; cc += 4) {
            float4 f = *(const float4*)(er + cc);
            int d0 = half * 64 + cc;
            *(__nv_bfloat16*)(sX + (d0 + 0) * XPITCH + r * 2) = __float2bfloat16(fmaxf(f.x, 0.f));
            *(__nv_bfloat16*)(sX + (d0 + 1) * XPITCH + r * 2) = __float2bfloat16(fmaxf(f.y, 0.f));
            *(__nv_bfloat16*)(sX + (d0 + 2) * XPITCH + r * 2) = __float2bfloat16(fmaxf(f.z, 0.f));
            *(__nv_bfloat16*)(sX + (d0 + 3) * XPITCH + r * 2) = __float2bfloat16(fmaxf(f.w, 0.f));
        }
    }

    // A fragments (W_ih) converted fp32 -> bf16 in-flight
    u32 a[4][8][4];
#pragma unroll
    for (int mt = 0; mt < 4; mt++) {
        int g1 = mt * 128 + w * 16 + (lane >> 2);
        int kc = (lane & 3) * 2;
#pragma unroll
        for (int kt = 0; kt < 8; kt++) {
            const float* Wp = Wih + g1 * DD + kt * 16 + kc;
            float2 f0 = *(const float2*)(Wp);
            float2 f1 = *(const float2*)(Wp + 8 * DD);
            float2 f2 = *(const float2*)(Wp + 8);
            float2 f3 = *(const float2*)(Wp + 8 * DD + 8);
            a[mt][kt][0] = pack_bf2(f0.x, f0.y);
            a[mt][kt][1] = pack_bf2(f1.x, f1.y);
            a[mt][kt][2] = pack_bf2(f2.x, f2.y);
            a[mt][kt][3] = pack_bf2(f3.x, f3.y);
        }
    }
    float bs[4][2];
#pragma unroll
    for (int mt = 0; mt < 4; mt++) {
        int g1 = mt * 128 + w * 16 + (lane >> 2);
        bs[mt][0] = bih[g1] + bhh[g1];
        bs[mt][1] = bih[g1 + 8] + bhh[g1 + 8];
    }
    __syncthreads();

    u32 xb = smem_u32(sX);
    const int jb = w * 16 + (lane >> 2);
    const int n0 = (lane & 3) * 2;

    for (int nt = 0; nt < 16; nt++) {
        u32 bf[8][2];
#pragma unroll
        for (int kt = 0; kt < 8; kt++)
            ldsm_x2t(bf[kt], xb + (kt * 16 + (lane & 15)) * XPITCH + nt * 16);
        float acc[4][4];
#pragma unroll
        for (int mt = 0; mt < 4; mt++) {
            acc[mt][0] = acc[mt][1] = acc[mt][2] = acc[mt][3] = 0.f;
#pragma unroll
            for (int kt = 0; kt < 8; kt++) mma16816(acc[mt], a[mt][kt], bf[kt]);
        }
#pragma unroll
        for (int e = 0; e < 4; e++) {
            int j = jb + (e >> 1) * 8;
            int tok = tokbase + nt * 8 + n0 + (e & 1);
            uint2 v = make_uint2(
                pack_bf2(acc[0][e] + bs[0][e >> 1], acc[1][e] + bs[1][e >> 1]),
                pack_bf2(acc[2][e] + bs[2][e >> 1], acc[3][e] + bs[3][e >> 1]));
            *(uint2*)(g_xg + (size_t)tok * G4 + j * 4) = v;
        }
    }
}

// ---------------- recurrent kernel: cp.async smem xg ring (no register ring) ----------------
__global__ void __launch_bounds__(256, 1)
lstm_rec(const int* __restrict__ tokens, const int* __restrict__ lengths,
         const float* __restrict__ onehot, const float* __restrict__ Whh,
         const float* __restrict__ h0, const float* __restrict__ c0,
         const float* __restrict__ linW, const float* __restrict__ linb,
         float* __restrict__ out) {
    __shared__ __align__(16) unsigned char hb[2][HH * 16];   // double-buffered h tile [k][s] bf16
    __shared__ int stok[BC * SS];
    __shared__ __align__(16) unsigned char sxg[3][8192];     // xg stage ring (cp.async target)

    const int tid = threadIdx.x;
    const int w = tid >> 5, lane = tid & 31;
    const int base_s = blockIdx.x * BC;

    for (int i = tid; i < BC * SS; i += 256) {
        int s = i >> 9, t = i & 511;
        stok[s * SS + t] = tokens[(size_t)(base_s + s) * SS + t];
    }
    for (int i = tid; i < HH * BC; i += 256) {
        int j = i >> 3, s = i & 7;
        *(__nv_bfloat16*)(hb[0] + j * 16 + s * 2) = __float2bfloat16(h0[j]);
    }
    // stok/hb[0] are read cross-thread below — staging must complete first.
    __syncthreads();

    // A fragments (W_hh) converted fp32 -> bf16 in-flight; register-resident for all steps
    u32 a[4][8][4];
#pragma unroll
    for (int mt = 0; mt < 4; mt++) {
        int g1 = mt * 128 + w * 16 + (lane >> 2);
        int kc = (lane & 3) * 2;
#pragma unroll
        for (int kt = 0; kt < 8; kt++) {
            const float* Wp = Whh + g1 * HH + kt * 16 + kc;
            float2 f0 = *(const float2*)(Wp);
            float2 f1 = *(const float2*)(Wp + 8 * HH);
            float2 f2 = *(const float2*)(Wp + 8);
            float2 f3 = *(const float2*)(Wp + 8 * HH + 8);
            a[mt][kt][0] = pack_bf2(f0.x, f0.y);
            a[mt][kt][1] = pack_bf2(f1.x, f1.y);
            a[mt][kt][2] = pack_bf2(f2.x, f2.y);
            a[mt][kt][3] = pack_bf2(f3.x, f3.y);
        }
    }

    const int jb = w * 16 + (lane >> 2);
    const int s0 = (lane & 3) * 2;
    u32 hbase0 = smem_u32(hb[0]);
    u32 hbase1 = smem_u32(hb[1]);
    u32 sxb = smem_u32(sxg) + tid * 32;   // this thread's 32B stage area (per slot)

    float c[4], hl[4];
    int len_[2];
    len_[0] = lengths[base_s + s0];
    len_[1] = lengths[base_s + s0 + 1];
#pragma unroll
    for (int e = 0; e < 4; e++) {
        c[e] = c0[jb + (e >> 1) * 8];
        hl[e] = 0.f;
    }

    // Prime the smem ring: data for t=0 (slot 0) and t=1 (slot 1), one group each.
#pragma unroll
    for (int slot = 0; slot < 2; slot++) {
#pragma unroll
        for (int e = 0; e < 4; e++) {
            int tok = stok[(s0 + (e & 1)) * SS + slot];
            cp_async8(sxb + slot * 8192 + e * 8,
                      g_xg + (size_t)tok * G4 + (jb + (e >> 1) * 8) * 4);
        }
        cp_commit();
    }

    int p = 0;
    int rs = 0, ws = 2;  // read slot (data t), write slot (data t+2)
    for (int t = 0; t < SS; t++) {
        // group for data t complete (only data t+1's group may remain outstanding)
        cp_wait1();
        const u64* xp = (const u64*)(uintptr_t)0;  // placeholder to keep types honest
        u64 xc[4];
        {
            const u64* q = (const u64*)((const unsigned char*)sxg + rs * 8192 + tid * 32);
#pragma unroll
            for (int e = 0; e < 4; e++) xc[e] = q[e];
        }
        (void)xp;

        // stage data for t+2 into ws (slot untouched by current read)
        if (t + 2 < SS) {
#pragma unroll
            for (int e = 0; e < 4; e++) {
                int tok = stok[(s0 + (e & 1)) * SS + t + 2];
                cp_async8(sxb + ws * 8192 + e * 8,
                          g_xg + (size_t)tok * G4 + (jb + (e >> 1) * 8) * 4);
            }
        }
        cp_commit();  // always commit to keep group accounting uniform

        u32 hrd = p ? hbase1 : hbase0;
        unsigned char* hwr = hb[p ^ 1];

        u32 bf[8][2];
#pragma unroll
        for (int kt = 0; kt < 8; kt++)
            ldsm_x2t(bf[kt], hrd + (kt * 16 + (lane & 15)) * 16);

        float acc[4][4];
#pragma unroll
        for (int mt = 0; mt < 4; mt++) {
            acc[mt][0] = acc[mt][1] = acc[mt][2] = acc[mt][3] = 0.f;
#pragma unroll
            for (int kt = 0; kt < 8; kt++) mma16816(acc[mt], a[mt][kt], bf[kt]);
        }

        float hv[4], ovv[4];
#pragma unroll
        for (int e = 0; e < 4; e++) {
            u32 lo = (u32)xc[e], hi = (u32)(xc[e] >> 32);
            float iv = sig_ap(acc[0][e] + bf_lo(lo));
            float fv = sig_ap(acc[1][e] + bf_hi(lo));
            float gv = tanh_ap(acc[2][e] + bf_lo(hi));
            float ov = sig_ap(acc[3][e] + bf_hi(hi));
            c[e] = fmaf(fv, c[e], iv * gv);
            hv[e] = ov * tanh_ap(c[e]);
            ovv[e] = ov;
        }
        *(u32*)(hwr + jb * 16 + s0 * 2) = pack_bf2(hv[0], hv[1]);
        *(u32*)(hwr + (jb + 8) * 16 + s0 * 2) = pack_bf2(hv[2], hv[3]);

        // rare accurate capture of h_last
        if (t == len_[0] - 1 || t == len_[1] - 1) {
#pragma unroll
            for (int e = 0; e < 4; e++)
                if (t == len_[e & 1] - 1)
                    hl[e] = fmaxf(ovv[e] * tanh_acc(c[e]), 0.f);
        }
        __syncthreads();  // h(t+1) tile visible; releases read buffer
        p ^= 1;
        rs = (rs == 2) ? 0 : rs + 1;
        ws = (ws == 2) ? 0 : ws + 1;
    }

    // head: reuse sxg region for hl exchange (ring is dead now; barrier above ordered it)
    float* shl = (float*)sxg;
#pragma unroll
    for (int e = 0; e < 4; e++)
        shl[(s0 + (e & 1)) * HH + jb + (e >> 1) * 8] = hl[e];
    __syncthreads();
    if (tid < BC * 2) {
        int s = tid >> 1, m = tid & 1;
        const float* wrow = linW + m * (HH + NOPS);
        float acc = linb[m];
#pragma unroll 8
        for (int jj = 0; jj < HH; jj++) acc = fmaf(shl[s * HH + jj], wrow[jj], acc);
#pragma unroll
        for (int pp = 0; pp < NOPS; pp++)
            acc = fmaf(onehot[(base_s + s) * NOPS + pp], wrow[HH + pp], acc);
        out[(base_s + s) * 2 + m] = acc;
    }
}

// ---------------- launch ----------------
extern "C" void kernel_launch(void* const* d_in, const int* in_sizes, int n_in,
                              void* d_out, int out_size) {
    const int* tokens = (const int*)d_in[0];
    const int* lengths = (const int*)d_in[1];
    const float* onehot = (const float*)d_in[2];
    const float* emb = (const float*)d_in[3];
    const float* Wih = (const float*)d_in[4];
    const float* Whh = (const float*)d_in[5];
    const float* bih = (const float*)d_in[6];
    const float* bhh = (const float*)d_in[7];
    const float* h0 = (const float*)d_in[8];
    const float* c0 = (const float*)d_in[9];
    const float* linW = (const float*)d_in[10];
    const float* linb = (const float*)d_in[11];
    float* out = (float*)d_out;

    phaseA_kernel<<<VSZ / 128, 256>>>(emb, Wih, bih, bhh);
    lstm_rec<<<NCTA, 256>>>(tokens, lengths, onehot, Whh, h0, c0, linW, linb, out);
}